// round 1
// baseline (speedup 1.0000x reference)
#include <cuda_runtime.h>
#include <math.h>

// Problem constants (fixed by the reference)
#define BB 8
#define NN 900
#define CC 256
#define HEADS 8
#define PP 4
#define HD 32
#define BH 200
#define BW 200
#define HW (BH*BW)
#define RADIUS 0.2f
#define QB 8          // queries per block
#define NBLK ((BB*NN)/QB)   // 900

__global__ __launch_bounds__(256, 4)
void deform_fused_kernel(
    const float* __restrict__ query,
    const float* __restrict__ memory,
    const float* __restrict__ refpts,
    const float* __restrict__ w_off,
    const float* __restrict__ b_off,
    const float* __restrict__ w_wt,
    const float* __restrict__ b_wt,
    const float* __restrict__ w_out,
    const float* __restrict__ b_out,
    float* __restrict__ out)
{
    __shared__ float q_s[QB][CC];        // 8 KB
    __shared__ float ow_s[QB][96];       // 3 KB : cols 0..63 = offset logits, 64..95 = weight logits
    __shared__ float sampw_s[QB][32][4]; // 4 KB : combined (softmax * bilinear * valid) weight
    __shared__ int   sampi_s[QB][32][4]; // 4 KB : clamped pixel index
    __shared__ float fused_s[QB][CC];    // 8 KB

    const int t = threadIdx.x;
    const int base = blockIdx.x * QB;    // flattened (b*N + n) of first query

    // ---------------- Phase 1: stage QB query rows ----------------
    #pragma unroll
    for (int i = t; i < QB*CC; i += 256) {
        int qq = i >> 8, k = i & 255;
        q_s[qq][k] = query[(size_t)(base + qq)*CC + k];
    }
    __syncthreads();

    // ---------------- Phase 2: offset+weight GEMV (96 cols) ----------------
    if (t < 96) {
        const bool is_off = (t < 64);
        const float* W = is_off ? w_off : w_wt;
        const int col  = is_off ? t : (t - 64);
        const int ldw  = is_off ? 64 : 32;
        float acc[QB];
        float bias = is_off ? b_off[col] : b_wt[col];
        #pragma unroll
        for (int qq = 0; qq < QB; qq++) acc[qq] = bias;

        for (int k4 = 0; k4 < CC; k4 += 4) {
            float w0 = W[(k4+0)*ldw + col];
            float w1 = W[(k4+1)*ldw + col];
            float w2 = W[(k4+2)*ldw + col];
            float w3 = W[(k4+3)*ldw + col];
            #pragma unroll
            for (int qq = 0; qq < QB; qq++) {
                float4 qv = *(const float4*)&q_s[qq][k4];
                acc[qq] += qv.x*w0 + qv.y*w1 + qv.z*w2 + qv.w*w3;
            }
        }
        #pragma unroll
        for (int qq = 0; qq < QB; qq++) ow_s[qq][t] = acc[qq];
    }
    __syncthreads();

    // ---------------- Phase 3: tanh offsets, softmax(P), bilinear setup ----
    // warp qq handles query qq; lane = h*P + p  (32 lanes = 8 heads x 4 pts)
    {
        const int qq   = t >> 5;
        const int lane = t & 31;
        const int flat = base + qq;
        float rx = refpts[(size_t)flat*2 + 0];
        float ry = refpts[(size_t)flat*2 + 1];

        float ox = tanhf(ow_s[qq][2*lane    ]) * RADIUS;
        float oy = tanhf(ow_s[qq][2*lane + 1]) * RADIUS;
        float x = (rx + ox) * (float)BW - 0.5f;
        float y = (ry + oy) * (float)BH - 0.5f;
        float x0f = floorf(x), y0f = floorf(y);
        int   x0 = (int)x0f,   y0 = (int)y0f;
        float fx = x - x0f,    fy = y - y0f;

        // softmax over the 4 lanes sharing a head (lanes 4h..4h+3)
        float lg = ow_s[qq][64 + lane];
        float m = lg;
        m = fmaxf(m, __shfl_xor_sync(0xffffffffu, m, 1));
        m = fmaxf(m, __shfl_xor_sync(0xffffffffu, m, 2));
        float e = expf(lg - m);
        float s = e;
        s += __shfl_xor_sync(0xffffffffu, s, 1);
        s += __shfl_xor_sync(0xffffffffu, s, 2);
        float wt = e / s;

        #pragma unroll
        for (int c = 0; c < 4; c++) {
            int xi = x0 + (c & 1);
            int yi = y0 + (c >> 1);
            bool valid = (xi >= 0) & (xi < BW) & (yi >= 0) & (yi < BH);
            float bwx = (c & 1)  ? fx : (1.f - fx);
            float bwy = (c >> 1) ? fy : (1.f - fy);
            int xc = min(max(xi, 0), BW - 1);
            int yc = min(max(yi, 0), BH - 1);
            sampw_s[qq][lane][c] = valid ? (wt * bwx * bwy) : 0.f;
            sampi_s[qq][lane][c] = yc * BW + xc;
        }
    }
    __syncthreads();

    // ---------------- Phase 4: gather + weighted sum over P ----------------
    // warp = one head (h = t>>5), lanes = hd dims -> coalesced 128B loads
    {
        const int h = t >> 5, d = t & 31;
        #pragma unroll
        for (int qq = 0; qq < QB; qq++) {
            const int flat = base + qq;
            const int b = flat / NN;
            const float* mb = memory + (size_t)b * HW * CC + h * HD + d;
            float acc = 0.f;
            #pragma unroll
            for (int p = 0; p < PP; p++) {
                const int hp = h * 4 + p;
                #pragma unroll
                for (int c = 0; c < 4; c++) {
                    float w  = sampw_s[qq][hp][c];   // warp-uniform
                    int  idx = sampi_s[qq][hp][c];   // warp-uniform
                    if (w != 0.f)                    // warp-uniform branch
                        acc += w * mb[(size_t)idx * CC];
                }
            }
            fused_s[qq][h * HD + d] = acc;
        }
    }
    __syncthreads();

    // ---------------- Phase 5: output projection [QBx256] @ [256x256] ------
    {
        float acc[QB];
        #pragma unroll
        for (int qq = 0; qq < QB; qq++) acc[qq] = 0.f;

        for (int k4 = 0; k4 < CC; k4 += 4) {
            float w0 = w_out[(size_t)(k4+0)*CC + t];
            float w1 = w_out[(size_t)(k4+1)*CC + t];
            float w2 = w_out[(size_t)(k4+2)*CC + t];
            float w3 = w_out[(size_t)(k4+3)*CC + t];
            #pragma unroll
            for (int qq = 0; qq < QB; qq++) {
                float4 fv = *(const float4*)&fused_s[qq][k4];
                acc[qq] += fv.x*w0 + fv.y*w1 + fv.z*w2 + fv.w*w3;
            }
        }
        const float bo = b_out[t];
        #pragma unroll
        for (int qq = 0; qq < QB; qq++)
            out[(size_t)(base + qq)*CC + t] = acc[qq] + bo;
    }
}

extern "C" void kernel_launch(void* const* d_in, const int* in_sizes, int n_in,
                              void* d_out, int out_size) {
    const float* query  = (const float*)d_in[0];
    const float* memory = (const float*)d_in[1];
    const float* refpts = (const float*)d_in[2];
    const float* w_off  = (const float*)d_in[3];
    const float* b_off  = (const float*)d_in[4];
    const float* w_wt   = (const float*)d_in[5];
    const float* b_wt   = (const float*)d_in[6];
    const float* w_out  = (const float*)d_in[7];
    const float* b_out  = (const float*)d_in[8];
    // d_in[9], d_in[10] = bev_h, bev_w (compile-time constants 200x200)

    deform_fused_kernel<<<NBLK, 256>>>(query, memory, refpts,
                                       w_off, b_off, w_wt, b_wt,
                                       w_out, b_out, (float*)d_out);
}

// round 2
// speedup vs baseline: 1.4743x; 1.4743x over previous
#include <cuda_runtime.h>
#include <math.h>

// Problem constants (fixed by the reference)
#define BB 8
#define NN 900
#define CC 256
#define HEADS 8
#define PP 4
#define HD 32
#define BH 200
#define BW 200
#define HW (BH*BW)
#define RADIUS 0.2f
#define QB 10                 // queries per block
#define NBLK ((BB*NN)/QB)     // 720 -> single wave at 5 blocks/SM on 148 SMs

__global__ __launch_bounds__(256, 5)
void deform_fused_kernel(
    const float* __restrict__ query,
    const float* __restrict__ memory,
    const float* __restrict__ refpts,
    const float* __restrict__ w_off,
    const float* __restrict__ b_off,
    const float* __restrict__ w_wt,
    const float* __restrict__ b_wt,
    const float* __restrict__ w_out,
    const float* __restrict__ b_out,
    float* __restrict__ out)
{
    // buf_s holds query rows for phases 1-2, then is reused for fused features
    // in phases 4-5 (q is dead after phase 2; syncthreads separate the uses).
    __shared__ float buf_s[QB][CC];      // 10 KB
    __shared__ float ow_s[QB][96];       // 3.75 KB
    __shared__ float sampw_s[QB][32][4]; // 5 KB
    __shared__ int   sampi_s[QB][32][4]; // 5 KB

    const int t = threadIdx.x;
    const int base = blockIdx.x * QB;    // flattened (b*N + n) of first query

    // ---------------- Phase 1: stage QB query rows ----------------
    #pragma unroll
    for (int i = t; i < QB*CC; i += 256) {
        int qq = i >> 8, k = i & 255;
        buf_s[qq][k] = query[(size_t)(base + qq)*CC + k];
    }
    __syncthreads();

    // ---------------- Phase 2: offset+weight GEMV (96 cols x 10 queries) ---
    // Two groups of 96 threads, each handling 5 queries -> 192 active threads.
    {
        int g = -1, tt = 0;
        if (t < 96)                    { g = 0; tt = t; }
        else if (t >= 128 && t < 224)  { g = 1; tt = t - 128; }
        if (g >= 0) {
            const int q0 = g * 5;
            const bool is_off = (tt < 64);
            const float* W = is_off ? w_off : w_wt;
            const int col  = is_off ? tt : (tt - 64);
            const int ldw  = is_off ? 64 : 32;
            float acc[5];
            const float bias = is_off ? b_off[col] : b_wt[col];
            #pragma unroll
            for (int qq = 0; qq < 5; qq++) acc[qq] = bias;

            for (int k4 = 0; k4 < CC; k4 += 4) {
                float w0 = W[(k4+0)*ldw + col];
                float w1 = W[(k4+1)*ldw + col];
                float w2 = W[(k4+2)*ldw + col];
                float w3 = W[(k4+3)*ldw + col];
                #pragma unroll
                for (int qq = 0; qq < 5; qq++) {
                    float4 qv = *(const float4*)&buf_s[q0+qq][k4];
                    acc[qq] += qv.x*w0 + qv.y*w1 + qv.z*w2 + qv.w*w3;
                }
            }
            #pragma unroll
            for (int qq = 0; qq < 5; qq++) ow_s[q0+qq][tt] = acc[qq];
        }
    }
    __syncthreads();

    // ---------------- Phase 3: tanh offsets, softmax(P), bilinear setup ----
    // warp handles queries (warp, warp+8); lane = h*P + p
    {
        const int lane = t & 31;
        for (int qq = (t >> 5); qq < QB; qq += 8) {
            const int flat = base + qq;
            float rx = refpts[(size_t)flat*2 + 0];
            float ry = refpts[(size_t)flat*2 + 1];

            float ox = tanhf(ow_s[qq][2*lane    ]) * RADIUS;
            float oy = tanhf(ow_s[qq][2*lane + 1]) * RADIUS;
            float x = (rx + ox) * (float)BW - 0.5f;
            float y = (ry + oy) * (float)BH - 0.5f;
            float x0f = floorf(x), y0f = floorf(y);
            int   x0 = (int)x0f,   y0 = (int)y0f;
            float fx = x - x0f,    fy = y - y0f;

            // softmax over the 4 lanes sharing a head
            float lg = ow_s[qq][64 + lane];
            float m = lg;
            m = fmaxf(m, __shfl_xor_sync(0xffffffffu, m, 1));
            m = fmaxf(m, __shfl_xor_sync(0xffffffffu, m, 2));
            float e = expf(lg - m);
            float s = e;
            s += __shfl_xor_sync(0xffffffffu, s, 1);
            s += __shfl_xor_sync(0xffffffffu, s, 2);
            float wt = e / s;

            #pragma unroll
            for (int c = 0; c < 4; c++) {
                int xi = x0 + (c & 1);
                int yi = y0 + (c >> 1);
                bool valid = (xi >= 0) & (xi < BW) & (yi >= 0) & (yi < BH);
                float bwx = (c & 1)  ? fx : (1.f - fx);
                float bwy = (c >> 1) ? fy : (1.f - fy);
                int xc = min(max(xi, 0), BW - 1);
                int yc = min(max(yi, 0), BH - 1);
                sampw_s[qq][lane][c] = valid ? (wt * bwx * bwy) : 0.f;
                sampi_s[qq][lane][c] = yc * BW + xc;
            }
        }
    }
    __syncthreads();

    // ---------------- Phase 4: gather + weighted sum over P ----------------
    // warp = one head (h = t>>5), lanes = hd dims -> coalesced 128B loads
    // Overwrites buf_s with fused features.
    {
        const int h = t >> 5, d = t & 31;
        for (int qq = 0; qq < QB; qq++) {
            const int flat = base + qq;
            const int b = flat / NN;
            const float* mb = memory + (size_t)b * HW * CC + h * HD + d;
            float acc = 0.f;
            #pragma unroll
            for (int p = 0; p < PP; p++) {
                const int hp = h * 4 + p;
                #pragma unroll
                for (int c = 0; c < 4; c++) {
                    float w  = sampw_s[qq][hp][c];   // warp-uniform
                    int  idx = sampi_s[qq][hp][c];   // warp-uniform
                    if (w != 0.f)                    // warp-uniform branch
                        acc += w * mb[(size_t)idx * CC];
                }
            }
            buf_s[qq][h * HD + d] = acc;
        }
    }
    __syncthreads();

    // ---------------- Phase 5: output projection [QBx256] @ [256x256] ------
    // Two passes of 5 accumulators to stay under the 51-reg cap.
    {
        const float bo = b_out[t];
        #pragma unroll 1
        for (int half = 0; half < 2; half++) {
            const int q0 = half * 5;
            float acc[5] = {0.f, 0.f, 0.f, 0.f, 0.f};
            #pragma unroll 2
            for (int k4 = 0; k4 < CC; k4 += 4) {
                float w0 = w_out[(size_t)(k4+0)*CC + t];
                float w1 = w_out[(size_t)(k4+1)*CC + t];
                float w2 = w_out[(size_t)(k4+2)*CC + t];
                float w3 = w_out[(size_t)(k4+3)*CC + t];
                #pragma unroll
                for (int qq = 0; qq < 5; qq++) {
                    float4 fv = *(const float4*)&buf_s[q0+qq][k4];
                    acc[qq] += fv.x*w0 + fv.y*w1 + fv.z*w2 + fv.w*w3;
                }
            }
            #pragma unroll
            for (int qq = 0; qq < 5; qq++)
                out[(size_t)(base + q0 + qq)*CC + t] = acc[qq] + bo;
        }
    }
}

extern "C" void kernel_launch(void* const* d_in, const int* in_sizes, int n_in,
                              void* d_out, int out_size) {
    const float* query  = (const float*)d_in[0];
    const float* memory = (const float*)d_in[1];
    const float* refpts = (const float*)d_in[2];
    const float* w_off  = (const float*)d_in[3];
    const float* b_off  = (const float*)d_in[4];
    const float* w_wt   = (const float*)d_in[5];
    const float* b_wt   = (const float*)d_in[6];
    const float* w_out  = (const float*)d_in[7];
    const float* b_out  = (const float*)d_in[8];
    // d_in[9], d_in[10] = bev_h, bev_w (compile-time constants 200x200)

    deform_fused_kernel<<<NBLK, 256>>>(query, memory, refpts,
                                       w_off, b_off, w_wt, b_wt,
                                       w_out, b_out, (float*)d_out);
}